// round 6
// baseline (speedup 1.0000x reference)
#include <cuda_runtime.h>
#include <cuda_fp16.h>
#include <cstdint>
#include <cmath>

#define CDIM 512
#define NDIM 512
#define BDIM 64
#define TT 4
#define BP 16           // BDIM / TT
#define HH 8
#define GDIM 64
#define EPSF 1e-5f
#define CN (CDIM*NDIM)  // 262144
#define MTOT_QKV 1536
#define BUFSZ 98304     // A0(16K)+A1(16K)+B0(32K)+B1(32K)
#define SMEM_DYN (2*BUFSZ)

// ---------------------------------------------------------------------------
// Scratch (device globals: allocation-free per harness rules)
// ---------------------------------------------------------------------------
__device__ __half        g_w2  [2ull*MTOT_QKV*CDIM];          // qkv weight splits
__device__ __half        g_wp2 [2ull*CDIM*CDIM];              // proj weight splits
__device__ __half        g_xt2 [2ull*BDIM*CN];                // x splits, [s][b][n][c]
__device__ float         g_pre [3ull*BDIM*CN];                // qkv pre-acts [w][b][c][n]
__device__ unsigned char g_spk [3ull*BDIM*CN];                // qkv spikes
__device__ float         g_attn[(unsigned long long)BDIM*CN];
__device__ unsigned char g_spk4[(unsigned long long)BDIM*CN];
__device__ __half        g_st  [(unsigned long long)BDIM*CN]; // spk4 fp16 [b][n][c]

// ---------------------------------------------------------------------------
// PTX helpers (baseline sm_80+, valid on compute_103 target)
// ---------------------------------------------------------------------------
__device__ __forceinline__ uint32_t smem_u32(const void* p) {
    uint32_t a;
    asm("{ .reg .u64 t; cvta.to.shared.u64 t, %1; cvt.u32.u64 %0, t; }" : "=r"(a) : "l"(p));
    return a;
}
#define LDSM4(r0,r1,r2,r3,addr) \
    asm volatile("ldmatrix.sync.aligned.m8n8.x4.shared.b16 {%0,%1,%2,%3}, [%4];" \
        : "=r"(r0),"=r"(r1),"=r"(r2),"=r"(r3) : "r"(addr))

__device__ __forceinline__ void mma16816(float* c, const uint32_t* a,
                                         uint32_t b0, uint32_t b1) {
    asm volatile("mma.sync.aligned.m16n8k16.row.col.f32.f16.f16.f32 "
        "{%0,%1,%2,%3}, {%4,%5,%6,%7}, {%8,%9}, {%0,%1,%2,%3};"
        : "+f"(c[0]), "+f"(c[1]), "+f"(c[2]), "+f"(c[3])
        : "r"(a[0]), "r"(a[1]), "r"(a[2]), "r"(a[3]), "r"(b0), "r"(b1));
}
__device__ __forceinline__ void cp_async16(uint32_t dst, const void* src) {
    asm volatile("cp.async.cg.shared.global [%0], [%1], 16;" :: "r"(dst), "l"(src));
}
__device__ __forceinline__ uint32_t swz(uint32_t bo) {
    return bo ^ (((bo >> 7) & 7u) << 4);
}

// ---------------------------------------------------------------------------
// Weight splits: w -> (fp16 hi, fp16 residual)
// ---------------------------------------------------------------------------
__global__ void wsplit_kernel(const float* __restrict__ wq, const float* __restrict__ wk,
                              const float* __restrict__ wv, const float* __restrict__ wp)
{
    int i = blockIdx.x * 256 + threadIdx.x;
    if (i < MTOT_QKV * CDIM) {
        int o = i >> 9;
        const float* src = (o < 512) ? wq : (o < 1024 ? wk : wv);
        float v = src[((o & 511) << 9) | (i & 511)];
        __half h0 = __float2half_rn(v);
        float r1 = v - __half2float(h0);
        g_w2[i] = h0;
        g_w2[(size_t)MTOT_QKV * CDIM + i] = __float2half_rn(r1);
    }
    if (i < CDIM * CDIM) {
        float v = wp[i];
        __half h0 = __float2half_rn(v);
        float r1 = v - __half2float(h0);
        g_wp2[i] = h0;
        g_wp2[(size_t)CDIM * CDIM + i] = __float2half_rn(r1);
    }
}

// ---------------------------------------------------------------------------
// x split + transpose: x[b][c][n] fp32 -> g_xt2[s][b][n][c] fp16 (2 splits)
// ---------------------------------------------------------------------------
__global__ void xsplit_kernel(const float* __restrict__ x)
{
    __shared__ float tile[32][33];
    const int b = blockIdx.z, c0 = blockIdx.y * 32, n0 = blockIdx.x * 32;
    const float* xb = x + (size_t)b * CN;
    const int tx = threadIdx.x, ty = threadIdx.y;   // 32 x 8
    #pragma unroll
    for (int r = 0; r < 4; ++r) {
        int cl = ty * 4 + r;
        tile[cl][tx] = xb[(size_t)(c0 + cl) * NDIM + n0 + tx];
    }
    __syncthreads();
    const size_t SEG = (size_t)BDIM * CN;
    #pragma unroll
    for (int r = 0; r < 4; ++r) {
        int nl = ty * 4 + r, cl = tx;
        float v = tile[cl][nl];
        __half h0 = __float2half_rn(v);
        float r1 = v - __half2float(h0);
        size_t o = ((size_t)b * NDIM + (n0 + nl)) * CDIM + c0 + cl;
        g_xt2[o] = h0;
        g_xt2[SEG + o] = __float2half_rn(r1);
    }
}

// spk4 u8 [b][c][n] -> fp16 transposed [b][n][c] (spikes exact in fp16)
__global__ void spkt_kernel()
{
    __shared__ unsigned char tile[32][33];
    const int b = blockIdx.z, c0 = blockIdx.y * 32, n0 = blockIdx.x * 32;
    const unsigned char* sb = g_spk4 + (size_t)b * CN;
    const int tx = threadIdx.x, ty = threadIdx.y;
    #pragma unroll
    for (int r = 0; r < 4; ++r) {
        int cl = ty * 4 + r;
        tile[cl][tx] = sb[(size_t)(c0 + cl) * NDIM + n0 + tx];
    }
    __syncthreads();
    #pragma unroll
    for (int r = 0; r < 4; ++r) {
        int nl = ty * 4 + r, cl = tx;
        g_st[((size_t)b * NDIM + (n0 + nl)) * CDIM + c0 + cl] =
            __float2half_rn((float)tile[cl][nl]);
    }
}

// ---------------------------------------------------------------------------
// HMMA split-GEMM + BN with shared-operand products.
// CTA: 128(M) x 256(N).  8 warps, 64x64 per warp.
// Per K-chunk(64) loads A0,A1,B0[,B1] once; issues products
//   A0*B0 + A1*B0 [+ A0*B1]  into one accumulator.
// ---------------------------------------------------------------------------
template<int NP>
__device__ __forceinline__ void load_chunk2(
    const __half* __restrict__ A0, const __half* __restrict__ A1,
    const __half* __restrict__ B0, const __half* __restrict__ B1,
    int mBase, int n0g, int kOff, uint32_t buf, int tid)
{
    const int nIters = (NP == 3) ? 24 : 16;   // 6144 / 4096 16B packets
    #pragma unroll
    for (int it = 0; it < nIters; ++it) {
        int i = tid + it * 256;
        int s = i & 7;
        const __half* g;
        uint32_t dst;
        if (i < 1024)      { int r = i >> 3;          g = A0 + (size_t)(mBase + r) * CDIM + kOff + s * 8; dst = 0u     + swz((uint32_t)(r*128 + s*16)); }
        else if (i < 2048) { int r = (i - 1024) >> 3; g = A1 + (size_t)(mBase + r) * CDIM + kOff + s * 8; dst = 16384u + swz((uint32_t)(r*128 + s*16)); }
        else if (i < 4096) { int r = (i - 2048) >> 3; g = B0 + (size_t)(n0g  + r) * CDIM + kOff + s * 8; dst = 32768u + swz((uint32_t)(r*128 + s*16)); }
        else               { int r = (i - 4096) >> 3; g = B1 + (size_t)(n0g  + r) * CDIM + kOff + s * 8; dst = 65536u + swz((uint32_t)(r*128 + s*16)); }
        cp_async16(buf + dst, g);
    }
}

template<int NP>
__global__ void __launch_bounds__(256, 1)
gemm_hmma2(const __half* __restrict__ A0g, const __half* __restrict__ A1g,
           const __half* __restrict__ B0g, const __half* __restrict__ B1g,
           float* __restrict__ Ybase,
           const float* __restrict__ bg, const float* __restrict__ bb,
           const float* __restrict__ bm, const float* __restrict__ bv,
           int isProj)
{
    extern __shared__ __align__(128) unsigned char dsm[];
    const uint32_t sbase = smem_u32(dsm);
    const int tid = threadIdx.x, lane = tid & 31, wid = tid >> 5;
    const int warpM = wid >> 2, warpN = wid & 3;       // 2 x 4 warps, 64x64 each
    const int b = blockIdx.z;
    const int mBase = blockIdx.y * 128;
    const int n0g   = blockIdx.x * 256;

    const __half* B0 = B0g + (size_t)b * CN;
    const __half* B1 = (NP == 3) ? (B1g + (size_t)b * CN) : B0;

    float acc[4][8][4];
    #pragma unroll
    for (int i = 0; i < 4; ++i)
        #pragma unroll
        for (int j = 0; j < 8; ++j)
            #pragma unroll
            for (int k = 0; k < 4; ++k) acc[i][j][k] = 0.f;

    load_chunk2<NP>(A0g, A1g, B0, B1, mBase, n0g, 0, sbase, tid);
    asm volatile("cp.async.commit_group;");

    int buf = 0;
    #pragma unroll 1
    for (int c = 0; c < 8; ++c) {
        if (c < 7) {
            load_chunk2<NP>(A0g, A1g, B0, B1, mBase, n0g, (c + 1) * 64,
                            sbase + (buf ^ 1) * BUFSZ, tid);
            asm volatile("cp.async.commit_group;");
            asm volatile("cp.async.wait_group 1;");
        } else {
            asm volatile("cp.async.wait_group 0;");
        }
        __syncthreads();

        const uint32_t base = sbase + buf * BUFSZ;
        #pragma unroll
        for (int ks = 0; ks < 4; ++ks) {
            uint32_t a0[4][4], a1[4][4];
            const int khA = ks * 16 + (lane >> 4) * 8;
            #pragma unroll
            for (int mt = 0; mt < 4; ++mt) {
                int row = warpM * 64 + mt * 16 + (lane & 7) + ((lane >> 3) & 1) * 8;
                uint32_t bo = swz((uint32_t)(row * 128 + khA * 2));
                LDSM4(a0[mt][0], a0[mt][1], a0[mt][2], a0[mt][3], base + bo);
                LDSM4(a1[mt][0], a1[mt][1], a1[mt][2], a1[mt][3], base + 16384u + bo);
            }
            const int khB = ks * 16 + ((lane >> 3) & 1) * 8;
            #pragma unroll
            for (int nt2 = 0; nt2 < 4; ++nt2) {
                int nrow = warpN * 64 + nt2 * 16 + (lane & 7) + ((lane >> 4) & 1) * 8;
                uint32_t bo = swz((uint32_t)(nrow * 128 + khB * 2));
                uint32_t rb[4];
                LDSM4(rb[0], rb[1], rb[2], rb[3], base + 32768u + bo);
                #pragma unroll
                for (int mt = 0; mt < 4; ++mt) {
                    mma16816(acc[mt][nt2*2+0], a0[mt], rb[0], rb[1]);
                    mma16816(acc[mt][nt2*2+1], a0[mt], rb[2], rb[3]);
                    mma16816(acc[mt][nt2*2+0], a1[mt], rb[0], rb[1]);
                    mma16816(acc[mt][nt2*2+1], a1[mt], rb[2], rb[3]);
                }
                if (NP == 3) {
                    LDSM4(rb[0], rb[1], rb[2], rb[3], base + 65536u + bo);
                    #pragma unroll
                    for (int mt = 0; mt < 4; ++mt) {
                        mma16816(acc[mt][nt2*2+0], a0[mt], rb[0], rb[1]);
                        mma16816(acc[mt][nt2*2+1], a0[mt], rb[2], rb[3]);
                    }
                }
            }
        }
        __syncthreads();
        buf ^= 1;
    }

    // epilogue: BN + store
    #pragma unroll
    for (int mt = 0; mt < 4; ++mt) {
        int o0 = mBase + warpM * 64 + mt * 16 + (lane >> 2);
        #pragma unroll
        for (int hf = 0; hf < 2; ++hf) {
            int o = o0 + hf * 8;
            int bnIdx; float* rowP;
            if (isProj) {
                bnIdx = 3 * CDIM + o;
                rowP  = Ybase + ((size_t)b * CDIM + o) * NDIM;
            } else {
                int w = o >> 9, cc = o & 511;
                bnIdx = w * CDIM + cc;
                rowP  = Ybase + (((size_t)w * BDIM + b) * CDIM + cc) * NDIM;
            }
            float inv  = bg[bnIdx] / sqrtf(bv[bnIdx] + EPSF);
            float bias = bb[bnIdx] - bm[bnIdx] * inv;
            #pragma unroll
            for (int nt = 0; nt < 8; ++nt) {
                int nn = n0g + warpN * 64 + nt * 8 + (lane & 3) * 2;
                float2 v;
                v.x = acc[mt][nt][hf * 2 + 0] * inv + bias;
                v.y = acc[mt][nt][hf * 2 + 1] * inv + bias;
                *(float2*)(rowP + nn) = v;
            }
        }
    }
}

// ---------------------------------------------------------------------------
// LIF scan (DRAM-roofline-bound, unchanged)
// ---------------------------------------------------------------------------
__global__ void lif_kernel(const float* __restrict__ pre,
                           unsigned char* __restrict__ spk,
                           int ntensors)
{
    size_t idx   = (size_t)blockIdx.x * blockDim.x + threadIdx.x;
    size_t total = (size_t)ntensors * BP * (CN / 4);
    if (idx >= total) return;
    int j4    = (int)(idx % (CN / 4));
    int rest  = (int)(idx / (CN / 4));
    int bp    = rest % BP;
    int which = rest / BP;

    const float* p = pre + (size_t)which * BDIM * CN;
    unsigned char* s = spk + (size_t)which * BDIM * CN;

    float4 mem = make_float4(0.f, 0.f, 0.f, 0.f);
    #pragma unroll
    for (int t = 0; t < TT; ++t) {
        size_t off = (size_t)(t * BP + bp) * CN + (size_t)j4 * 4;
        float4 xi = *(const float4*)(p + off);
        mem.x = mem.x * 0.5f + xi.x;
        mem.y = mem.y * 0.5f + xi.y;
        mem.z = mem.z * 0.5f + xi.z;
        mem.w = mem.w * 0.5f + xi.w;
        uchar4 sp;
        sp.x = mem.x > 1.0f; if (sp.x) mem.x = 0.f;
        sp.y = mem.y > 1.0f; if (sp.y) mem.y = 0.f;
        sp.z = mem.z > 1.0f; if (sp.z) mem.z = 0.f;
        sp.w = mem.w > 1.0f; if (sp.w) mem.w = 0.f;
        *(uchar4*)(s + off) = sp;
    }
}

// ---------------------------------------------------------------------------
// Spiking attention (bit-exact popcount reordering, unchanged)
// ---------------------------------------------------------------------------
__global__ void __launch_bounds__(256)
attn_kernel(const unsigned char* __restrict__ spk,
            float* __restrict__ attn)
{
    const int bh = blockIdx.x;
    const int b  = bh / HH;
    const int h  = bh % HH;
    const size_t head_off = ((size_t)b * CDIM + (size_t)h * GDIM) * NDIM;
    const unsigned char* qS = spk + 0ull * BDIM * CN + head_off;
    const unsigned char* kS = spk + 1ull * BDIM * CN + head_off;
    const unsigned char* vS = spk + 2ull * BDIM * CN + head_off;

    __shared__ unsigned int kb[64][16];
    __shared__ unsigned int vb[64][16];
    __shared__ float        Ms[64][64];
    __shared__ unsigned char qs[64][128];

    const int tid  = threadIdx.x;
    const int lane = tid & 31;
    const int warp = tid >> 5;

    #pragma unroll
    for (int r = 0; r < 8; ++r) {
        int e = warp * 8 + r;
        #pragma unroll
        for (int w = 0; w < 16; ++w) {
            unsigned int bkk = __ballot_sync(0xffffffffu, kS[(size_t)e * NDIM + w * 32 + lane] != 0);
            unsigned int bvv = __ballot_sync(0xffffffffu, vS[(size_t)e * NDIM + w * 32 + lane] != 0);
            if (lane == 0) { kb[e][w] = bkk; vb[e][w] = bvv; }
        }
    }
    __syncthreads();

    {
        int e  = tid >> 2;
        int d0 = (tid & 3) * 16;
        unsigned int kr[16];
        #pragma unroll
        for (int w = 0; w < 16; ++w) kr[w] = kb[e][w];
        #pragma unroll
        for (int dd = 0; dd < 16; ++dd) {
            int d = d0 + dd;
            int s = 0;
            #pragma unroll
            for (int w = 0; w < 16; ++w) s += __popc(kr[w] & vb[d][w]);
            Ms[e][d] = (float)s * 0.125f;
        }
    }
    __syncthreads();

    const int nLocal = tid & 127;
    const int d0     = (tid >> 7) * 32;
    float* outp = attn + head_off;

    for (int ch = 0; ch < 4; ++ch) {
        const int nb = ch * 128;
        for (int w = tid; w < 2048; w += 256) {
            int e = w >> 5, nl4 = (w & 31) << 2;
            *(unsigned int*)&qs[e][nl4] =
                *(const unsigned int*)(qS + (size_t)e * NDIM + nb + nl4);
        }
        __syncthreads();

        float acc[32];
        #pragma unroll
        for (int j = 0; j < 32; ++j) acc[j] = 0.f;

        #pragma unroll 4
        for (int e = 0; e < 64; ++e) {
            float qv = (float)qs[e][nLocal];
            #pragma unroll
            for (int j = 0; j < 32; ++j)
                acc[j] += qv * Ms[e][d0 + j];
        }
        #pragma unroll
        for (int j = 0; j < 32; ++j)
            outp[(size_t)(d0 + j) * NDIM + nb + nLocal] = acc[j];
        __syncthreads();
    }
}

// ---------------------------------------------------------------------------
// launch
// ---------------------------------------------------------------------------
extern "C" void kernel_launch(void* const* d_in, const int* in_sizes, int n_in,
                              void* d_out, int out_size)
{
    (void)in_sizes; (void)n_in; (void)out_size;
    const float* x  = (const float*)d_in[0];
    const float* wq = (const float*)d_in[1];
    const float* wk = (const float*)d_in[2];
    const float* wv = (const float*)d_in[3];
    const float* wp = (const float*)d_in[4];
    const float* bg = (const float*)d_in[5];
    const float* bb = (const float*)d_in[6];
    const float* bm = (const float*)d_in[7];
    const float* bv = (const float*)d_in[8];
    float* out = (float*)d_out;

    cudaFuncSetAttribute(gemm_hmma2<3>, cudaFuncAttributeMaxDynamicSharedMemorySize, SMEM_DYN);
    cudaFuncSetAttribute(gemm_hmma2<2>, cudaFuncAttributeMaxDynamicSharedMemorySize, SMEM_DYN);

    float* pre;  unsigned char* spk;
    float* attn; unsigned char* spk4;
    __half *w2, *wp2, *xt2, *st;
    cudaGetSymbolAddress((void**)&pre,  g_pre);
    cudaGetSymbolAddress((void**)&spk,  g_spk);
    cudaGetSymbolAddress((void**)&attn, g_attn);
    cudaGetSymbolAddress((void**)&spk4, g_spk4);
    cudaGetSymbolAddress((void**)&w2,   g_w2);
    cudaGetSymbolAddress((void**)&wp2,  g_wp2);
    cudaGetSymbolAddress((void**)&xt2,  g_xt2);
    cudaGetSymbolAddress((void**)&st,   g_st);

    // 1. splits
    wsplit_kernel<<<(MTOT_QKV*CDIM + 255)/256, 256>>>(wq, wk, wv, wp);
    xsplit_kernel<<<dim3(16,16,BDIM), dim3(32,8)>>>(x);

    // 2. fused qkv GEMM+BN: acc = w0*x0 + w1*x0 + w0*x1 (shared-operand loads)
    gemm_hmma2<3><<<dim3(NDIM/256, MTOT_QKV/128, BDIM), 256, SMEM_DYN>>>(
        w2, w2 + (size_t)MTOT_QKV*CDIM, xt2, xt2 + (size_t)BDIM*CN,
        pre, bg, bb, bm, bv, 0);

    // 3. LIF over q/k/v pre-activations
    {
        size_t total = 3ull * BP * (CN / 4);
        lif_kernel<<<(int)((total + 255)/256), 256>>>(pre, spk, 3);
    }

    // 4. spiking attention (exact popcount path)
    attn_kernel<<<BDIM * HH, 256>>>(spk, attn);

    // 5. LIF over attention output
    {
        size_t total = 1ull * BP * (CN / 4);
        lif_kernel<<<(int)((total + 255)/256), 256>>>(attn, spk4, 1);
    }

    // 6. spike transpose to fp16 [b][n][c]
    spkt_kernel<<<dim3(16,16,BDIM), dim3(32,8)>>>();

    // 7. proj GEMM+BN: acc = w0*s + w1*s (spikes exact in fp16)
    gemm_hmma2<2><<<dim3(NDIM/256, CDIM/128, BDIM), 256, SMEM_DYN>>>(
        wp2, wp2 + (size_t)CDIM*CDIM, st, st,
        out, bg, bb, bm, bv, 1);
}